// round 7
// baseline (speedup 1.0000x reference)
#include <cuda_runtime.h>
#include <math.h>

#define DIMV       512
#define HEADS      8
#define DIM_KEY    32
#define NUM_KEYS   256
#define TOPK       16
#define TOKENS     1024
#define FULLMASK   0xffffffffu

// scratch (device globals; no allocs)
__device__ float g_qp0[TOKENS * DIMV];       // q partial (k 0..255)
__device__ float g_qp1[TOKENS * DIMV];       // q partial (k 256..511)
__device__ float g_sim[HEADS * TOKENS * NUM_KEYS];
__device__ float g_wdT[DIMV * NUM_KEYS];
__device__ float g_Dp0[TOKENS * NUM_KEYS];
__device__ float g_Dp1[TOKENS * NUM_KEYS];
__device__ float g_S[TOKENS * NUM_KEYS];
__device__ float g_op0[TOKENS * DIMV];
__device__ float g_op1[TOKENS * DIMV];

// ---------------------------------------------------------------------------
// SGEMM block: 64x64 C-tile, 256 threads, 4x4/thread, BK=16, double-buffered.
// A row stride LDA (elements); A (and optional A2, summed) pre-offset to the
// k-range start; B pre-offset likewise. NT = number of 16-wide k tiles.
// smem: As[2][16][72] + Bs[2][16][64] = 17408 B
// ---------------------------------------------------------------------------
#define GEMM_SMEM_BYTES (2*16*72*4 + 2*16*64*4)

template<int N, int LDA, int NT, bool SCALE, bool DUAL>
__device__ __forceinline__ void sgemm64(
    const float* __restrict__ A, const float* __restrict__ A2,
    const float* __restrict__ B,
    float* __restrict__ C, int m0, int n0, char* smem_raw)
{
    typedef float AsT[16][72];
    typedef float BsT[16][64];
    AsT* As = (AsT*)smem_raw;
    BsT* Bs = (BsT*)(smem_raw + 2 * 16 * 72 * 4);

    const int tid = threadIdx.x;          // 0..255
    const int tx = tid & 15;
    const int ty = tid >> 4;

    const int arow = tid >> 2;            // 0..63
    const int akq  = (tid & 3) * 4;       // 0,4,8,12
    const int bkr  = tid >> 4;            // 0..15
    const int bnq  = (tid & 15) * 4;

    float acc[4][4];
#pragma unroll
    for (int i = 0; i < 4; i++)
#pragma unroll
        for (int j = 0; j < 4; j++) acc[i][j] = 0.0f;

    float4 arg, brg;
    {
        const float* ap = &A[(size_t)(m0 + arow) * LDA + akq];
        arg = *reinterpret_cast<const float4*>(ap);
        if (DUAL) {
            float4 a2 = *reinterpret_cast<const float4*>(
                &A2[(size_t)(m0 + arow) * LDA + akq]);
            arg.x += a2.x; arg.y += a2.y; arg.z += a2.z; arg.w += a2.w;
        }
    }
    brg = *reinterpret_cast<const float4*>(&B[(size_t)bkr * N + n0 + bnq]);

    int buf = 0;
#pragma unroll 1
    for (int kt = 0; kt < NT; kt++) {
        As[buf][akq + 0][arow] = arg.x;
        As[buf][akq + 1][arow] = arg.y;
        As[buf][akq + 2][arow] = arg.z;
        As[buf][akq + 3][arow] = arg.w;
        *reinterpret_cast<float4*>(&Bs[buf][bkr][bnq]) = brg;
        __syncthreads();

        if (kt + 1 < NT) {
            int k0 = (kt + 1) * 16;
            arg = *reinterpret_cast<const float4*>(
                &A[(size_t)(m0 + arow) * LDA + k0 + akq]);
            if (DUAL) {
                float4 a2 = *reinterpret_cast<const float4*>(
                    &A2[(size_t)(m0 + arow) * LDA + k0 + akq]);
                arg.x += a2.x; arg.y += a2.y; arg.z += a2.z; arg.w += a2.w;
            }
            brg = *reinterpret_cast<const float4*>(
                &B[(size_t)(k0 + bkr) * N + n0 + bnq]);
        }

        float4 ac = *reinterpret_cast<const float4*>(&As[buf][0][ty * 4]);
        float4 bc = *reinterpret_cast<const float4*>(&Bs[buf][0][tx * 4]);
#pragma unroll
        for (int k = 0; k < 16; k++) {
            float4 an, bn;
            if (k < 15) {
                an = *reinterpret_cast<const float4*>(&As[buf][k + 1][ty * 4]);
                bn = *reinterpret_cast<const float4*>(&Bs[buf][k + 1][tx * 4]);
            }
            acc[0][0] += ac.x * bc.x; acc[0][1] += ac.x * bc.y;
            acc[0][2] += ac.x * bc.z; acc[0][3] += ac.x * bc.w;
            acc[1][0] += ac.y * bc.x; acc[1][1] += ac.y * bc.y;
            acc[1][2] += ac.y * bc.z; acc[1][3] += ac.y * bc.w;
            acc[2][0] += ac.z * bc.x; acc[2][1] += ac.z * bc.y;
            acc[2][2] += ac.z * bc.z; acc[2][3] += ac.z * bc.w;
            acc[3][0] += ac.w * bc.x; acc[3][1] += ac.w * bc.y;
            acc[3][2] += ac.w * bc.z; acc[3][3] += ac.w * bc.w;
            if (k < 15) { ac = an; bc = bn; }
        }
        buf ^= 1;
    }

    const float scale = SCALE ? 0.99999500003749981f : 1.0f;
#pragma unroll
    for (int i = 0; i < 4; i++) {
        int row = m0 + ty * 4 + i;
        float4 f;
        f.x = acc[i][0] * scale; f.y = acc[i][1] * scale;
        f.z = acc[i][2] * scale; f.w = acc[i][3] * scale;
        *reinterpret_cast<float4*>(&C[(size_t)row * N + n0 + tx * 4]) = f;
    }
}

// ---------------------------------------------------------------------------
// K1: blocks 0..255 -> G1 split-K=2 partials; 256..383 -> transpose wdown.
// ---------------------------------------------------------------------------
__global__ void __launch_bounds__(256)
k1_fused(const float* __restrict__ x, const float* __restrict__ wq,
         const float* __restrict__ wdown)
{
    __shared__ __align__(16) char smem[GEMM_SMEM_BYTES];
    int bid = blockIdx.x;
    if (bid < 256) {
        int nb = bid & 7;
        int mb = (bid >> 3) & 15;
        int sp = bid >> 7;                   // 0/1
        int koff = sp * 256;
        float* outp = sp ? g_qp1 : g_qp0;
        // A = x (LDA=512) offset by koff cols; B = wq offset by koff rows
        sgemm64<DIMV, DIMV, 16, true, false>(
            x + koff, nullptr, wq + (size_t)koff * DIMV,
            outp, mb * 64, nb * 64, smem);
    } else {
        int b = bid - 256;
        int d0 = (b & 15) * 32;
        int e0 = (b >> 4) * 32;
        float (*t)[33] = (float(*)[33])smem;
        int tx = threadIdx.x & 31, ty = threadIdx.x >> 5;   // 32 x 8
#pragma unroll
        for (int i = 0; i < 4; i++)
            t[ty + i * 8][tx] = wdown[(size_t)(e0 + ty + i * 8) * DIMV + d0 + tx];
        __syncthreads();
#pragma unroll
        for (int i = 0; i < 4; i++)
            g_wdT[(size_t)(d0 + ty + i * 8) * NUM_KEYS + e0 + tx] = t[tx][ty + i * 8];
    }
}

// ---------------------------------------------------------------------------
// K2: blocks 0..127 -> G2 split-K=2 (D partials, A = qp0+qp1);
//     blocks 128..255 -> sim (64-token tiles, q = qp0+qp1).
// ---------------------------------------------------------------------------
#define SIM_SMEM_BYTES (DIM_KEY*NUM_KEYS*4 + DIM_KEY*64*4)
#define K2_SMEM (SIM_SMEM_BYTES > GEMM_SMEM_BYTES ? SIM_SMEM_BYTES : GEMM_SMEM_BYTES)

__global__ void __launch_bounds__(256)
k2_fused(const float* __restrict__ keys)
{
    __shared__ __align__(16) char smem[K2_SMEM];
    int bid = blockIdx.x;
    int tid = threadIdx.x;

    if (bid < 128) {
        // G2: 16 m-tiles x 4 n-tiles x 2 splits
        int nb = bid & 3;
        int mb = (bid >> 2) & 15;
        int sp = bid >> 6;
        int koff = sp * 256;
        float* outp = sp ? g_Dp1 : g_Dp0;
        sgemm64<NUM_KEYS, DIMV, 16, false, true>(
            g_qp0 + koff, g_qp1 + koff, g_wdT + (size_t)koff * NUM_KEYS,
            outp, mb * 64, nb * 64, smem);
        return;
    }

    // sim: 128 blocks, each (64 tokens x 256 keys) for one head
    int b = bid - 128;
    int t0 = (b & 15) * 64;
    int h = b >> 4;

    float (*Ks)[NUM_KEYS] = (float(*)[NUM_KEYS])smem;
    float (*Qs)[64] = (float(*)[64])(smem + DIM_KEY * NUM_KEYS * 4);

    {
        const float4* kp = reinterpret_cast<const float4*>(
            keys + (size_t)((h * NUM_KEYS + tid) * 2) * DIM_KEY);
#pragma unroll
        for (int i = 0; i < 8; i++) {
            float4 f = kp[i];
            Ks[4 * i + 0][tid] = f.x;
            Ks[4 * i + 1][tid] = f.y;
            Ks[4 * i + 2][tid] = f.z;
            Ks[4 * i + 3][tid] = f.w;
        }
    }
    {
        int tl = tid & 63;
        int d0 = (tid >> 6) * 8;
        size_t off = (size_t)(t0 + tl) * DIMV + h * DIM_KEY + d0;
        float4 f0 = *reinterpret_cast<const float4*>(g_qp0 + off);
        float4 f1 = *reinterpret_cast<const float4*>(g_qp0 + off + 4);
        float4 e0 = *reinterpret_cast<const float4*>(g_qp1 + off);
        float4 e1 = *reinterpret_cast<const float4*>(g_qp1 + off + 4);
        f0.x += e0.x; f0.y += e0.y; f0.z += e0.z; f0.w += e0.w;
        f1.x += e1.x; f1.y += e1.y; f1.z += e1.z; f1.w += e1.w;
        Qs[d0 + 0][tl] = f0.x; Qs[d0 + 1][tl] = f0.y;
        Qs[d0 + 2][tl] = f0.z; Qs[d0 + 3][tl] = f0.w;
        Qs[d0 + 4][tl] = f1.x; Qs[d0 + 5][tl] = f1.y;
        Qs[d0 + 6][tl] = f1.z; Qs[d0 + 7][tl] = f1.w;
    }
    __syncthreads();

    int kg = tid & 15;
    int tg = tid >> 4;
    float acc[4][16];
#pragma unroll
    for (int i = 0; i < 4; i++)
#pragma unroll
        for (int j = 0; j < 16; j++) acc[i][j] = 0.0f;

#pragma unroll
    for (int d = 0; d < DIM_KEY; d++) {
        float4 qv = *reinterpret_cast<const float4*>(&Qs[d][tg * 4]);
        float q4[4] = {qv.x, qv.y, qv.z, qv.w};
        float kv[16];
#pragma unroll
        for (int jj = 0; jj < 4; jj++) {
            float4 kk = *reinterpret_cast<const float4*>(&Ks[d][kg * 16 + jj * 4]);
            kv[jj * 4 + 0] = kk.x; kv[jj * 4 + 1] = kk.y;
            kv[jj * 4 + 2] = kk.z; kv[jj * 4 + 3] = kk.w;
        }
#pragma unroll
        for (int i = 0; i < 4; i++)
#pragma unroll
            for (int j = 0; j < 16; j++) acc[i][j] += q4[i] * kv[j];
    }

#pragma unroll
    for (int i = 0; i < 4; i++) {
        int t = t0 + tg * 4 + i;
        float* op = g_sim + ((size_t)h * TOKENS + t) * NUM_KEYS + kg * 16;
#pragma unroll
        for (int jj = 0; jj < 4; jj++) {
            float4 f;
            f.x = acc[i][jj * 4 + 0]; f.y = acc[i][jj * 4 + 1];
            f.z = acc[i][jj * 4 + 2]; f.w = acc[i][jj * 4 + 3];
            *reinterpret_cast<float4*>(op + jj * 4) = f;
        }
    }
}

// ---------------------------------------------------------------------------
// K3: selection (deterministic, no atomics). D = Dp0 + Dp1 at gather points.
// ---------------------------------------------------------------------------
__device__ __forceinline__ float gelu_tanh(float x) {
    float x3 = x * x * x;
    float t = tanhf(0.7978845608028654f * (x + 0.044715f * x3));
    return 0.5f * x * (1.0f + t);
}

__device__ __forceinline__ void warp_top16(float* val, int lane,
                                           float* out_v, int* out_i)
{
#pragma unroll
    for (int r = 0; r < TOPK; r++) {
        float bv = val[0]; int bs = 0;
#pragma unroll
        for (int s = 1; s < 8; s++)
            if (val[s] > bv) { bv = val[s]; bs = s; }
        int bp = lane + (bs << 5);
#pragma unroll
        for (int off = 16; off > 0; off >>= 1) {
            float ov = __shfl_xor_sync(FULLMASK, bv, off);
            int   op = __shfl_xor_sync(FULLMASK, bp, off);
            if (ov > bv || (ov == bv && op < bp)) { bv = ov; bp = op; }
        }
        out_v[r] = bv;
        out_i[r] = bp;
        if ((bp & 31) == lane) {
            int ws = bp >> 5;
#pragma unroll
            for (int s = 0; s < 8; s++)
                if (s == ws) val[s] = -INFINITY;
        }
    }
}

__global__ void __launch_bounds__(256) select_kernel()
{
    int t = blockIdx.x;
    int tid = threadIdx.x;
    int w = tid >> 5;
    int lane = tid & 31;

    __shared__ float v0s[HEADS][TOPK];
    __shared__ float i0s[HEADS][TOPK];
    __shared__ int   pk_all[HEADS * TOPK];
    __shared__ float g_all[HEADS * TOPK];

    float val[8];
    {
        const float* simrow = g_sim + ((size_t)w * TOKENS + t) * NUM_KEYS;
#pragma unroll
        for (int s = 0; s < 8; s++)
            val[s] = simrow[lane + (s << 5)];
    }

    float v0[TOPK]; int i0[TOPK];
    warp_top16(val, lane, v0, i0);
    if (lane == 0) {
#pragma unroll
        for (int r = 0; r < TOPK; r++) {
            v0s[w][r] = v0[r];
            i0s[w][r] = (float)i0[r];
        }
    }
    __syncwarp();

    float val2[8];
#pragma unroll
    for (int s = 0; s < 8; s++) {
        int p = lane + (s << 5);
        val2[s] = v0s[w][p >> 4] + i0s[w][p & 15];
    }

    float scf[TOPK]; int pk[TOPK];
    warp_top16(val2, lane, scf, pk);

    float myscf = -INFINITY; int mypk = 0;
#pragma unroll
    for (int r = 0; r < TOPK; r++)
        if (lane == r) { myscf = scf[r]; mypk = pk[r]; }

    float m = scf[0];
#pragma unroll
    for (int r = 1; r < TOPK; r++) m = fmaxf(m, scf[r]);
    float mye = expf(myscf - m);
    float esum = mye;
#pragma unroll
    for (int off = 16; off > 0; off >>= 1)
        esum += __shfl_xor_sync(FULLMASK, esum, off);

    if (lane < TOPK) {
        size_t di = (size_t)t * NUM_KEYS + mypk;
        float dv = g_Dp0[di] + g_Dp1[di];
        float g = gelu_tanh(dv) * (mye / esum);
        pk_all[w * TOPK + lane] = mypk;
        g_all[w * TOPK + lane] = g;
    }
    __syncthreads();

    float s = 0.0f;
#pragma unroll
    for (int i = 0; i < HEADS * TOPK; i++) {
        s += (pk_all[i] == tid) ? g_all[i] : 0.0f;
    }
    g_S[(size_t)t * NUM_KEYS + tid] = s;
}

// ---------------------------------------------------------------------------
// K4: G3 split-K=2 partials: out_p = S @ wup[:256]
// ---------------------------------------------------------------------------
__global__ void __launch_bounds__(256)
k4_gemm(const float* __restrict__ wup)
{
    __shared__ __align__(16) char smem[GEMM_SMEM_BYTES];
    int bid = blockIdx.x;
    int nb = bid & 7;
    int mb = (bid >> 3) & 15;
    int sp = bid >> 7;
    int koff = sp * 128;
    float* outp = sp ? g_op1 : g_op0;
    sgemm64<DIMV, NUM_KEYS, 8, false, false>(
        g_S + koff, nullptr, wup + (size_t)koff * DIMV,
        outp, mb * 64, nb * 64, smem);
}

// ---------------------------------------------------------------------------
// K5: out = op0 + op1 (float4)
// ---------------------------------------------------------------------------
__global__ void __launch_bounds__(256)
k5_reduce(float* __restrict__ out)
{
    int i = blockIdx.x * 256 + threadIdx.x;   // float4 index
    float4 a = reinterpret_cast<const float4*>(g_op0)[i];
    float4 b = reinterpret_cast<const float4*>(g_op1)[i];
    a.x += b.x; a.y += b.y; a.z += b.z; a.w += b.w;
    reinterpret_cast<float4*>(out)[i] = a;
}

// ---------------------------------------------------------------------------
extern "C" void kernel_launch(void* const* d_in, const int* in_sizes, int n_in,
                              void* d_out, int out_size)
{
    const float* x     = (const float*)d_in[0];
    const float* w_q   = (const float*)d_in[1];
    const float* keys  = (const float*)d_in[2];
    const float* wdown = (const float*)d_in[3];
    const float* wup   = (const float*)d_in[4];
    float* out = (float*)d_out;

    k1_fused<<<384, 256>>>(x, w_q, wdown);
    k2_fused<<<256, 256>>>(keys);
    select_kernel<<<TOKENS, 256>>>();
    k4_gemm<<<256, 256>>>(wup);
    k5_reduce<<<(TOKENS * DIMV / 4) / 256, 256>>>(out);
}

// round 8
// speedup vs baseline: 1.1783x; 1.1783x over previous
#include <cuda_runtime.h>
#include <cuda_fp16.h>
#include <mma.h>
#include <math.h>

using namespace nvcuda;

#define DIMV       512
#define HEADS      8
#define DIM_KEY    32
#define NUM_KEYS   256
#define TOPK       16
#define TOKENS     1024
#define FULLMASK   0xffffffffu

// scratch (device globals; no allocs)
__device__ __align__(16) float  g_qp0[TOKENS * DIMV];
__device__ __align__(16) float  g_qp1[TOKENS * DIMV];
__device__ __align__(16) float  g_sim[HEADS * TOKENS * NUM_KEYS];
__device__ __align__(16) __half g_wdTh[DIMV * NUM_KEYS];     // wdown[:256]^T fp16
__device__ __align__(16) float  g_D[TOKENS * NUM_KEYS];
__device__ __align__(16) __half g_Sh[TOKENS * NUM_KEYS];

// ---------------------------------------------------------------------------
// fp32 SGEMM 64x64 (for G1 only): 256 threads, 4x4/thread, BK=16, dbl-buffered
// ---------------------------------------------------------------------------
#define GEMM_SMEM_BYTES (2*16*72*4 + 2*16*64*4)

template<int N, int LDA, int NT, bool SCALE>
__device__ __forceinline__ void sgemm64(
    const float* __restrict__ A, const float* __restrict__ B,
    float* __restrict__ C, int m0, int n0, char* smem_raw)
{
    typedef float AsT[16][72];
    typedef float BsT[16][64];
    AsT* As = (AsT*)smem_raw;
    BsT* Bs = (BsT*)(smem_raw + 2 * 16 * 72 * 4);

    const int tid = threadIdx.x;
    const int tx = tid & 15;
    const int ty = tid >> 4;
    const int arow = tid >> 2;
    const int akq  = (tid & 3) * 4;
    const int bkr  = tid >> 4;
    const int bnq  = (tid & 15) * 4;

    float acc[4][4];
#pragma unroll
    for (int i = 0; i < 4; i++)
#pragma unroll
        for (int j = 0; j < 4; j++) acc[i][j] = 0.0f;

    float4 arg = *reinterpret_cast<const float4*>(&A[(size_t)(m0 + arow) * LDA + akq]);
    float4 brg = *reinterpret_cast<const float4*>(&B[(size_t)bkr * N + n0 + bnq]);

    int buf = 0;
#pragma unroll 1
    for (int kt = 0; kt < NT; kt++) {
        As[buf][akq + 0][arow] = arg.x;
        As[buf][akq + 1][arow] = arg.y;
        As[buf][akq + 2][arow] = arg.z;
        As[buf][akq + 3][arow] = arg.w;
        *reinterpret_cast<float4*>(&Bs[buf][bkr][bnq]) = brg;
        __syncthreads();

        if (kt + 1 < NT) {
            int k0 = (kt + 1) * 16;
            arg = *reinterpret_cast<const float4*>(
                &A[(size_t)(m0 + arow) * LDA + k0 + akq]);
            brg = *reinterpret_cast<const float4*>(
                &B[(size_t)(k0 + bkr) * N + n0 + bnq]);
        }

        float4 ac = *reinterpret_cast<const float4*>(&As[buf][0][ty * 4]);
        float4 bc = *reinterpret_cast<const float4*>(&Bs[buf][0][tx * 4]);
#pragma unroll
        for (int k = 0; k < 16; k++) {
            float4 an, bn;
            if (k < 15) {
                an = *reinterpret_cast<const float4*>(&As[buf][k + 1][ty * 4]);
                bn = *reinterpret_cast<const float4*>(&Bs[buf][k + 1][tx * 4]);
            }
            acc[0][0] += ac.x * bc.x; acc[0][1] += ac.x * bc.y;
            acc[0][2] += ac.x * bc.z; acc[0][3] += ac.x * bc.w;
            acc[1][0] += ac.y * bc.x; acc[1][1] += ac.y * bc.y;
            acc[1][2] += ac.y * bc.z; acc[1][3] += ac.y * bc.w;
            acc[2][0] += ac.z * bc.x; acc[2][1] += ac.z * bc.y;
            acc[2][2] += ac.z * bc.z; acc[2][3] += ac.z * bc.w;
            acc[3][0] += ac.w * bc.x; acc[3][1] += ac.w * bc.y;
            acc[3][2] += ac.w * bc.z; acc[3][3] += ac.w * bc.w;
            if (k < 15) { ac = an; bc = bn; }
        }
        buf ^= 1;
    }

    const float scale = SCALE ? 0.99999500003749981f : 1.0f;
#pragma unroll
    for (int i = 0; i < 4; i++) {
        int row = m0 + ty * 4 + i;
        float4 f;
        f.x = acc[i][0] * scale; f.y = acc[i][1] * scale;
        f.z = acc[i][2] * scale; f.w = acc[i][3] * scale;
        *reinterpret_cast<float4*>(&C[(size_t)row * N + n0 + tx * 4]) = f;
    }
}

// ---------------------------------------------------------------------------
// fp16 WMMA GEMM 64x64 tile: 256 threads (8 warps, 2x4), warp tile 32x16,
// fp32 accumulate. A: half src OR dual-fp32 (summed+converted). B: half or f32.
// smem: As[64][32] half (4096B) + Bs[16][80] half (2560B)
// ---------------------------------------------------------------------------
#define HGEMM_SMEM_BYTES (64*32*2 + 16*80*2)

template<int K, int LDA, int NTOT, bool AHALF, bool BHALF>
__device__ __forceinline__ void hgemm64(
    const void* __restrict__ Aa, const void* __restrict__ Ab,
    const void* __restrict__ Bv,
    float* __restrict__ C, int m0, int n0, char* smem_raw)
{
    typedef __half AsT[64][32];
    typedef __half BsT[16][80];
    AsT& As = *(AsT*)smem_raw;
    BsT& Bs = *(BsT*)(smem_raw + 64 * 32 * 2);

    const int tid = threadIdx.x;
    const int w = tid >> 5;
    const int wm = w >> 2;          // 0..1
    const int wn = w & 3;           // 0..3

    wmma::fragment<wmma::accumulator, 16, 16, 16, float> acc[2];
    wmma::fill_fragment(acc[0], 0.0f);
    wmma::fill_fragment(acc[1], 0.0f);

#pragma unroll 1
    for (int kt = 0; kt < K / 16; kt++) {
        int k0 = kt * 16;
        __syncthreads();
        if (tid < 128) {
            int row = tid >> 1;
            int kq = (tid & 1) * 8;
            if (AHALF) {
                uint4 v = *reinterpret_cast<const uint4*>(
                    (const __half*)Aa + (size_t)(m0 + row) * LDA + k0 + kq);
                *reinterpret_cast<uint4*>(&As[row][kq]) = v;
            } else {
                const float* a0 = (const float*)Aa + (size_t)(m0 + row) * LDA + k0 + kq;
                const float* a1 = (const float*)Ab + (size_t)(m0 + row) * LDA + k0 + kq;
                float4 f0 = *reinterpret_cast<const float4*>(a0);
                float4 f1 = *reinterpret_cast<const float4*>(a0 + 4);
                float4 e0 = *reinterpret_cast<const float4*>(a1);
                float4 e1 = *reinterpret_cast<const float4*>(a1 + 4);
                __half2* dst = reinterpret_cast<__half2*>(&As[row][kq]);
                dst[0] = __floats2half2_rn(f0.x + e0.x, f0.y + e0.y);
                dst[1] = __floats2half2_rn(f0.z + e0.z, f0.w + e0.w);
                dst[2] = __floats2half2_rn(f1.x + e1.x, f1.y + e1.y);
                dst[3] = __floats2half2_rn(f1.z + e1.z, f1.w + e1.w);
            }
        } else {
            int t2 = tid - 128;
            int row = t2 >> 3;
            int nq = (t2 & 7) * 8;
            if (BHALF) {
                uint4 v = *reinterpret_cast<const uint4*>(
                    (const __half*)Bv + (size_t)(k0 + row) * NTOT + n0 + nq);
                *reinterpret_cast<uint4*>(&Bs[row][nq]) = v;
            } else {
                const float* b = (const float*)Bv + (size_t)(k0 + row) * NTOT + n0 + nq;
                float4 f0 = *reinterpret_cast<const float4*>(b);
                float4 f1 = *reinterpret_cast<const float4*>(b + 4);
                __half2* dst = reinterpret_cast<__half2*>(&Bs[row][nq]);
                dst[0] = __floats2half2_rn(f0.x, f0.y);
                dst[1] = __floats2half2_rn(f0.z, f0.w);
                dst[2] = __floats2half2_rn(f1.x, f1.y);
                dst[3] = __floats2half2_rn(f1.z, f1.w);
            }
        }
        __syncthreads();

        wmma::fragment<wmma::matrix_a, 16, 16, 16, __half, wmma::row_major> af;
        wmma::fragment<wmma::matrix_b, 16, 16, 16, __half, wmma::row_major> bf;
        wmma::load_matrix_sync(bf, &Bs[0][16 * wn], 80);
#pragma unroll
        for (int i = 0; i < 2; i++) {
            wmma::load_matrix_sync(af, &As[32 * wm + 16 * i][0], 32);
            wmma::mma_sync(acc[i], af, bf, acc[i]);
        }
    }

#pragma unroll
    for (int i = 0; i < 2; i++) {
        wmma::store_matrix_sync(
            &C[(size_t)(m0 + 32 * wm + 16 * i) * NTOT + n0 + 16 * wn],
            acc[i], NTOT, wmma::mem_row_major);
    }
}

// ---------------------------------------------------------------------------
// K1: blocks 0..255 -> G1 split-K=2 fp32; 256..383 -> transpose wdown -> half.
// ---------------------------------------------------------------------------
__global__ void __launch_bounds__(256)
k1_fused(const float* __restrict__ x, const float* __restrict__ wq,
         const float* __restrict__ wdown)
{
    __shared__ __align__(16) char smem[GEMM_SMEM_BYTES];
    int bid = blockIdx.x;
    if (bid < 256) {
        int nb = bid & 7;
        int mb = (bid >> 3) & 15;
        int sp = bid >> 7;
        int koff = sp * 256;
        float* outp = sp ? g_qp1 : g_qp0;
        sgemm64<DIMV, DIMV, 16, true>(
            x + koff, wq + (size_t)koff * DIMV, outp, mb * 64, nb * 64, smem);
    } else {
        int b = bid - 256;
        int d0 = (b & 15) * 32;
        int e0 = (b >> 4) * 32;
        float (*t)[33] = (float(*)[33])smem;
        int tx = threadIdx.x & 31, ty = threadIdx.x >> 5;   // 32 x 8
#pragma unroll
        for (int i = 0; i < 4; i++)
            t[ty + i * 8][tx] = wdown[(size_t)(e0 + ty + i * 8) * DIMV + d0 + tx];
        __syncthreads();
#pragma unroll
        for (int i = 0; i < 4; i++)
            g_wdTh[(size_t)(d0 + ty + i * 8) * NUM_KEYS + e0 + tx] =
                __float2half_rn(t[tx][ty + i * 8]);
    }
}

// ---------------------------------------------------------------------------
// K2: blocks 0..63 -> G2 (D = (qp0+qp1) @ wdTh, fp16 MMA, fp32 out);
//     blocks 64..191 -> sim (fp32, 64-token tiles).
// ---------------------------------------------------------------------------
#define SIM_SMEM_BYTES (DIM_KEY*NUM_KEYS*4 + DIM_KEY*64*4)
#define K2_SMEM (SIM_SMEM_BYTES > HGEMM_SMEM_BYTES ? SIM_SMEM_BYTES : HGEMM_SMEM_BYTES)

__global__ void __launch_bounds__(256)
k2_fused(const float* __restrict__ keys)
{
    __shared__ __align__(16) char smem[K2_SMEM];
    int bid = blockIdx.x;
    int tid = threadIdx.x;

    if (bid < 64) {
        int mb = bid >> 2, nb = bid & 3;
        hgemm64<DIMV, DIMV, NUM_KEYS, false, true>(
            g_qp0, g_qp1, g_wdTh, g_D, mb * 64, nb * 64, smem);
        return;
    }

    // sim
    int b = bid - 64;
    int t0 = (b & 15) * 64;
    int h = b >> 4;

    float (*Ks)[NUM_KEYS] = (float(*)[NUM_KEYS])smem;
    float (*Qs)[64] = (float(*)[64])(smem + DIM_KEY * NUM_KEYS * 4);

    {
        const float4* kp = reinterpret_cast<const float4*>(
            keys + (size_t)((h * NUM_KEYS + tid) * 2) * DIM_KEY);
#pragma unroll
        for (int i = 0; i < 8; i++) {
            float4 f = kp[i];
            Ks[4 * i + 0][tid] = f.x;
            Ks[4 * i + 1][tid] = f.y;
            Ks[4 * i + 2][tid] = f.z;
            Ks[4 * i + 3][tid] = f.w;
        }
    }
    {
        int tl = tid & 63;
        int d0 = (tid >> 6) * 8;
        size_t off = (size_t)(t0 + tl) * DIMV + h * DIM_KEY + d0;
        float4 f0 = *reinterpret_cast<const float4*>(g_qp0 + off);
        float4 f1 = *reinterpret_cast<const float4*>(g_qp0 + off + 4);
        float4 e0 = *reinterpret_cast<const float4*>(g_qp1 + off);
        float4 e1 = *reinterpret_cast<const float4*>(g_qp1 + off + 4);
        f0.x += e0.x; f0.y += e0.y; f0.z += e0.z; f0.w += e0.w;
        f1.x += e1.x; f1.y += e1.y; f1.z += e1.z; f1.w += e1.w;
        Qs[d0 + 0][tl] = f0.x; Qs[d0 + 1][tl] = f0.y;
        Qs[d0 + 2][tl] = f0.z; Qs[d0 + 3][tl] = f0.w;
        Qs[d0 + 4][tl] = f1.x; Qs[d0 + 5][tl] = f1.y;
        Qs[d0 + 6][tl] = f1.z; Qs[d0 + 7][tl] = f1.w;
    }
    __syncthreads();

    int kg = tid & 15;
    int tg = tid >> 4;
    float acc[4][16];
#pragma unroll
    for (int i = 0; i < 4; i++)
#pragma unroll
        for (int j = 0; j < 16; j++) acc[i][j] = 0.0f;

#pragma unroll
    for (int d = 0; d < DIM_KEY; d++) {
        float4 qv = *reinterpret_cast<const float4*>(&Qs[d][tg * 4]);
        float q4[4] = {qv.x, qv.y, qv.z, qv.w};
        float kv[16];
#pragma unroll
        for (int jj = 0; jj < 4; jj++) {
            float4 kk = *reinterpret_cast<const float4*>(&Ks[d][kg * 16 + jj * 4]);
            kv[jj * 4 + 0] = kk.x; kv[jj * 4 + 1] = kk.y;
            kv[jj * 4 + 2] = kk.z; kv[jj * 4 + 3] = kk.w;
        }
#pragma unroll
        for (int i = 0; i < 4; i++)
#pragma unroll
            for (int j = 0; j < 16; j++) acc[i][j] += q4[i] * kv[j];
    }

#pragma unroll
    for (int i = 0; i < 4; i++) {
        int t = t0 + tg * 4 + i;
        float* op = g_sim + ((size_t)h * TOKENS + t) * NUM_KEYS + kg * 16;
#pragma unroll
        for (int jj = 0; jj < 4; jj++) {
            float4 f;
            f.x = acc[i][jj * 4 + 0]; f.y = acc[i][jj * 4 + 1];
            f.z = acc[i][jj * 4 + 2]; f.w = acc[i][jj * 4 + 3];
            *reinterpret_cast<float4*>(op + jj * 4) = f;
        }
    }
}

// ---------------------------------------------------------------------------
// K3: selection with structural fast path.
// ---------------------------------------------------------------------------
__device__ __forceinline__ float gelu_tanh(float x) {
    float x3 = x * x * x;
    float t = tanhf(0.7978845608028654f * (x + 0.044715f * x3));
    return 0.5f * x * (1.0f + t);
}

__device__ __forceinline__ void warp_top16(float* val, int lane,
                                           float* out_v, int* out_i)
{
#pragma unroll
    for (int r = 0; r < TOPK; r++) {
        float bv = val[0]; int bs = 0;
#pragma unroll
        for (int s = 1; s < 8; s++)
            if (val[s] > bv) { bv = val[s]; bs = s; }
        int bp = lane + (bs << 5);
#pragma unroll
        for (int off = 16; off > 0; off >>= 1) {
            float ov = __shfl_xor_sync(FULLMASK, bv, off);
            int   op = __shfl_xor_sync(FULLMASK, bp, off);
            if (ov > bv || (ov == bv && op < bp)) { bv = ov; bp = op; }
        }
        out_v[r] = bv;
        out_i[r] = bp;
        if ((bp & 31) == lane) {
            int ws = bp >> 5;
#pragma unroll
            for (int s = 0; s < 8; s++)
                if (s == ws) val[s] = -INFINITY;
        }
    }
}

__global__ void __launch_bounds__(256) select_kernel()
{
    int t = blockIdx.x;
    int tid = threadIdx.x;
    int w = tid >> 5;
    int lane = tid & 31;

    __shared__ float sS[NUM_KEYS];
    __shared__ float v0s[HEADS][TOPK];
    __shared__ float i0s[HEADS][TOPK];

    sS[tid] = 0.0f;
    __syncthreads();

    float val[8];
    {
        const float* simrow = g_sim + ((size_t)w * TOKENS + t) * NUM_KEYS;
#pragma unroll
        for (int s = 0; s < 8; s++)
            val[s] = simrow[lane + (s << 5)];
    }

    float v0[TOPK]; int i0[TOPK];
    warp_top16(val, lane, v0, i0);

    // top-2 of the index values + position of the max
    int imax = -1, i2nd = -1, jst = 0;
#pragma unroll
    for (int j = 0; j < TOPK; j++) {
        int v = i0[j];
        if (v > imax) { i2nd = imax; imax = v; jst = j; }
        else if (v > i2nd) i2nd = v;
    }
    float spread = v0[0] - v0[TOPK - 1];
    bool fast = (float)(imax - i2nd) > spread;

    if (fast) {
        // combined top-16 is exactly column j*: pk[r] = r*16 + jst,
        // scores = v0[r] + imax  ->  softmax == softmax(v0)
        float myv = -INFINITY;
#pragma unroll
        for (int r = 0; r < TOPK; r++)
            if (lane == r) myv = v0[r];
        float mye = expf(myv - v0[0]);
        float esum = mye;
#pragma unroll
        for (int off = 16; off > 0; off >>= 1)
            esum += __shfl_xor_sync(FULLMASK, esum, off);
        if (lane < TOPK) {
            int pk = lane * TOPK + jst;
            float dv = g_D[(size_t)t * NUM_KEYS + pk];
            float g = gelu_tanh(dv) * (mye / esum);
            atomicAdd(&sS[pk], g);
        }
    } else {
        if (lane == 0) {
#pragma unroll
            for (int r = 0; r < TOPK; r++) {
                v0s[w][r] = v0[r];
                i0s[w][r] = (float)i0[r];
            }
        }
        __syncwarp();
        float val2[8];
#pragma unroll
        for (int s = 0; s < 8; s++) {
            int p = lane + (s << 5);
            val2[s] = v0s[w][p >> 4] + i0s[w][p & 15];
        }
        float scf[TOPK]; int pk[TOPK];
        warp_top16(val2, lane, scf, pk);

        float myscf = -INFINITY; int mypk = 0;
#pragma unroll
        for (int r = 0; r < TOPK; r++)
            if (lane == r) { myscf = scf[r]; mypk = pk[r]; }
        float m = scf[0];
#pragma unroll
        for (int r = 1; r < TOPK; r++) m = fmaxf(m, scf[r]);
        float mye = expf(myscf - m);
        float esum = mye;
#pragma unroll
        for (int off = 16; off > 0; off >>= 1)
            esum += __shfl_xor_sync(FULLMASK, esum, off);
        if (lane < TOPK) {
            float dv = g_D[(size_t)t * NUM_KEYS + mypk];
            float g = gelu_tanh(dv) * (mye / esum);
            atomicAdd(&sS[mypk], g);
        }
    }
    __syncthreads();

    g_Sh[(size_t)t * NUM_KEYS + tid] = __float2half_rn(sS[tid]);
}

// ---------------------------------------------------------------------------
// K4: out = Sh @ wup[:256]  (fp16 MMA, fp32 out, no split)
// ---------------------------------------------------------------------------
__global__ void __launch_bounds__(256)
k4_gemm(const float* __restrict__ wup, float* __restrict__ out)
{
    __shared__ __align__(16) char smem[HGEMM_SMEM_BYTES];
    int bid = blockIdx.x;
    int mb = bid >> 3, nb = bid & 7;
    hgemm64<NUM_KEYS, NUM_KEYS, DIMV, true, false>(
        g_Sh, nullptr, wup, out, mb * 64, nb * 64, smem);
}

// ---------------------------------------------------------------------------
extern "C" void kernel_launch(void* const* d_in, const int* in_sizes, int n_in,
                              void* d_out, int out_size)
{
    const float* x     = (const float*)d_in[0];
    const float* w_q   = (const float*)d_in[1];
    const float* keys  = (const float*)d_in[2];
    const float* wdown = (const float*)d_in[3];
    const float* wup   = (const float*)d_in[4];
    float* out = (float*)d_out;

    k1_fused<<<384, 256>>>(x, w_q, wdown);
    k2_fused<<<192, 256>>>(keys);
    select_kernel<<<TOKENS, 256>>>();
    k4_gemm<<<128, 256>>>(wup, out);
}

// round 9
// speedup vs baseline: 1.3632x; 1.1570x over previous
#include <cuda_runtime.h>
#include <cuda_fp16.h>
#include <mma.h>
#include <math.h>

using namespace nvcuda;

#define DIMV       512
#define HEADS      8
#define DIM_KEY    32
#define NUM_KEYS   256
#define TOPK       16
#define TOKENS     1024
#define FULLMASK   0xffffffffu

// scratch (device globals; no allocs)
__device__ __align__(16) float  g_qp0[TOKENS * DIMV];
__device__ __align__(16) float  g_qp1[TOKENS * DIMV];
__device__ __align__(16) float  g_sim[HEADS * TOKENS * NUM_KEYS];
__device__ __align__(16) __half g_wdTh[DIMV * NUM_KEYS];
__device__ __align__(16) float  g_D[TOKENS * NUM_KEYS];
__device__ __align__(16) __half g_Sh[TOKENS * NUM_KEYS];

// ---------------------------------------------------------------------------
// fp32 SGEMM 64x64 (G1): 256 threads, 4x4/thread, BK=16, double-buffered.
// ---------------------------------------------------------------------------
#define GEMM_SMEM_BYTES (2*16*72*4 + 2*16*64*4)

template<int N, int LDA, int NT, bool SCALE>
__device__ __forceinline__ void sgemm64(
    const float* __restrict__ A, const float* __restrict__ B,
    float* __restrict__ C, int m0, int n0, char* smem_raw)
{
    typedef float AsT[16][72];
    typedef float BsT[16][64];
    AsT* As = (AsT*)smem_raw;
    BsT* Bs = (BsT*)(smem_raw + 2 * 16 * 72 * 4);

    const int tid = threadIdx.x;
    const int tx = tid & 15;
    const int ty = tid >> 4;
    const int arow = tid >> 2;
    const int akq  = (tid & 3) * 4;
    const int bkr  = tid >> 4;
    const int bnq  = (tid & 15) * 4;

    float acc[4][4];
#pragma unroll
    for (int i = 0; i < 4; i++)
#pragma unroll
        for (int j = 0; j < 4; j++) acc[i][j] = 0.0f;

    float4 arg = *reinterpret_cast<const float4*>(&A[(size_t)(m0 + arow) * LDA + akq]);
    float4 brg = *reinterpret_cast<const float4*>(&B[(size_t)bkr * N + n0 + bnq]);

    int buf = 0;
#pragma unroll 1
    for (int kt = 0; kt < NT; kt++) {
        As[buf][akq + 0][arow] = arg.x;
        As[buf][akq + 1][arow] = arg.y;
        As[buf][akq + 2][arow] = arg.z;
        As[buf][akq + 3][arow] = arg.w;
        *reinterpret_cast<float4*>(&Bs[buf][bkr][bnq]) = brg;
        __syncthreads();

        if (kt + 1 < NT) {
            int k0 = (kt + 1) * 16;
            arg = *reinterpret_cast<const float4*>(
                &A[(size_t)(m0 + arow) * LDA + k0 + akq]);
            brg = *reinterpret_cast<const float4*>(
                &B[(size_t)(k0 + bkr) * N + n0 + bnq]);
        }

        float4 ac = *reinterpret_cast<const float4*>(&As[buf][0][ty * 4]);
        float4 bc = *reinterpret_cast<const float4*>(&Bs[buf][0][tx * 4]);
#pragma unroll
        for (int k = 0; k < 16; k++) {
            float4 an, bn;
            if (k < 15) {
                an = *reinterpret_cast<const float4*>(&As[buf][k + 1][ty * 4]);
                bn = *reinterpret_cast<const float4*>(&Bs[buf][k + 1][tx * 4]);
            }
            acc[0][0] += ac.x * bc.x; acc[0][1] += ac.x * bc.y;
            acc[0][2] += ac.x * bc.z; acc[0][3] += ac.x * bc.w;
            acc[1][0] += ac.y * bc.x; acc[1][1] += ac.y * bc.y;
            acc[1][2] += ac.y * bc.z; acc[1][3] += ac.y * bc.w;
            acc[2][0] += ac.z * bc.x; acc[2][1] += ac.z * bc.y;
            acc[2][2] += ac.z * bc.z; acc[2][3] += ac.z * bc.w;
            acc[3][0] += ac.w * bc.x; acc[3][1] += ac.w * bc.y;
            acc[3][2] += ac.w * bc.z; acc[3][3] += ac.w * bc.w;
            if (k < 15) { ac = an; bc = bn; }
        }
        buf ^= 1;
    }

    const float scale = SCALE ? 0.99999500003749981f : 1.0f;
#pragma unroll
    for (int i = 0; i < 4; i++) {
        int row = m0 + ty * 4 + i;
        float4 f;
        f.x = acc[i][0] * scale; f.y = acc[i][1] * scale;
        f.z = acc[i][2] * scale; f.w = acc[i][3] * scale;
        *reinterpret_cast<float4*>(&C[(size_t)row * N + n0 + tx * 4]) = f;
    }
}

// ---------------------------------------------------------------------------
// fp16 WMMA GEMM, double-buffered: 64x64 C tile, 256 threads, BK=32.
// A: [M][K] half, or dual fp32 (summed + converted). B: [K][NTOT] half or f32.
// smem: As[2][64][40] half (10240B) + Bs[2][32][72] half (9216B) = 19456B
// 8 warps, warp tile 16x32 (wm=w>>1, wn=w&1), 2 fp32 acc frags / warp.
// ---------------------------------------------------------------------------
#define HGEMM_SMEM_BYTES (2*64*40*2 + 2*32*72*2)

__device__ __forceinline__ uint4 pack8h(float4 f0, float4 f1) {
    __half2 h0 = __floats2half2_rn(f0.x, f0.y);
    __half2 h1 = __floats2half2_rn(f0.z, f0.w);
    __half2 h2 = __floats2half2_rn(f1.x, f1.y);
    __half2 h3 = __floats2half2_rn(f1.z, f1.w);
    uint4 u;
    u.x = *reinterpret_cast<unsigned*>(&h0);
    u.y = *reinterpret_cast<unsigned*>(&h1);
    u.z = *reinterpret_cast<unsigned*>(&h2);
    u.w = *reinterpret_cast<unsigned*>(&h3);
    return u;
}

template<int K, int NTOT, bool AHALF, bool BHALF>
__device__ __forceinline__ void hgemm_db(
    const void* __restrict__ Aa, const void* __restrict__ Ab,
    const void* __restrict__ Bv,
    float* __restrict__ C, int m0, int n0, char* smem_raw)
{
    typedef __half AsT[64][40];
    typedef __half BsT[32][72];
    AsT* As = (AsT*)smem_raw;
    BsT* Bs = (BsT*)(smem_raw + 2 * 64 * 40 * 2);

    const int tid = threadIdx.x;
    const int w = tid >> 5;
    const int wm = w >> 1;          // 0..3
    const int wn = w & 1;           // 0..1

    const int arow = tid >> 2;            // 0..63
    const int akq  = (tid & 3) * 8;       // 0,8,16,24
    const int brow = tid >> 3;            // 0..31
    const int bnq  = (tid & 7) * 8;       // 0..56

    wmma::fragment<wmma::accumulator, 16, 16, 16, float> acc[2];
    wmma::fill_fragment(acc[0], 0.0f);
    wmma::fill_fragment(acc[1], 0.0f);

    uint4 areg, breg;
    // initial loads (k0 = 0)
    if (AHALF) {
        areg = *reinterpret_cast<const uint4*>(
            (const __half*)Aa + (size_t)(m0 + arow) * K + akq);
    } else {
        const float* a0 = (const float*)Aa + (size_t)(m0 + arow) * K + akq;
        const float* a1 = (const float*)Ab + (size_t)(m0 + arow) * K + akq;
        float4 f0 = *reinterpret_cast<const float4*>(a0);
        float4 f1 = *reinterpret_cast<const float4*>(a0 + 4);
        float4 e0 = *reinterpret_cast<const float4*>(a1);
        float4 e1 = *reinterpret_cast<const float4*>(a1 + 4);
        f0.x += e0.x; f0.y += e0.y; f0.z += e0.z; f0.w += e0.w;
        f1.x += e1.x; f1.y += e1.y; f1.z += e1.z; f1.w += e1.w;
        areg = pack8h(f0, f1);
    }
    if (BHALF) {
        breg = *reinterpret_cast<const uint4*>(
            (const __half*)Bv + (size_t)brow * NTOT + n0 + bnq);
    } else {
        const float* b = (const float*)Bv + (size_t)brow * NTOT + n0 + bnq;
        breg = pack8h(*reinterpret_cast<const float4*>(b),
                      *reinterpret_cast<const float4*>(b + 4));
    }

    int buf = 0;
    const int NT = K / 32;
#pragma unroll 1
    for (int kt = 0; kt < NT; kt++) {
        *reinterpret_cast<uint4*>(&As[buf][arow][akq]) = areg;
        *reinterpret_cast<uint4*>(&Bs[buf][brow][bnq]) = breg;
        __syncthreads();

        if (kt + 1 < NT) {
            int k0 = (kt + 1) * 32;
            if (AHALF) {
                areg = *reinterpret_cast<const uint4*>(
                    (const __half*)Aa + (size_t)(m0 + arow) * K + k0 + akq);
            } else {
                const float* a0 = (const float*)Aa + (size_t)(m0 + arow) * K + k0 + akq;
                const float* a1 = (const float*)Ab + (size_t)(m0 + arow) * K + k0 + akq;
                float4 f0 = *reinterpret_cast<const float4*>(a0);
                float4 f1 = *reinterpret_cast<const float4*>(a0 + 4);
                float4 e0 = *reinterpret_cast<const float4*>(a1);
                float4 e1 = *reinterpret_cast<const float4*>(a1 + 4);
                f0.x += e0.x; f0.y += e0.y; f0.z += e0.z; f0.w += e0.w;
                f1.x += e1.x; f1.y += e1.y; f1.z += e1.z; f1.w += e1.w;
                areg = pack8h(f0, f1);
            }
            if (BHALF) {
                breg = *reinterpret_cast<const uint4*>(
                    (const __half*)Bv + (size_t)(k0 + brow) * NTOT + n0 + bnq);
            } else {
                const float* b = (const float*)Bv + (size_t)(k0 + brow) * NTOT + n0 + bnq;
                breg = pack8h(*reinterpret_cast<const float4*>(b),
                              *reinterpret_cast<const float4*>(b + 4));
            }
        }

        wmma::fragment<wmma::matrix_a, 16, 16, 16, __half, wmma::row_major> af;
        wmma::fragment<wmma::matrix_b, 16, 16, 16, __half, wmma::row_major> bf;
#pragma unroll
        for (int ks = 0; ks < 2; ks++) {
            wmma::load_matrix_sync(af, &As[buf][wm * 16][ks * 16], 40);
#pragma unroll
            for (int i = 0; i < 2; i++) {
                wmma::load_matrix_sync(bf, &Bs[buf][ks * 16][wn * 32 + i * 16], 72);
                wmma::mma_sync(acc[i], af, bf, acc[i]);
            }
        }
        buf ^= 1;
    }

#pragma unroll
    for (int i = 0; i < 2; i++) {
        wmma::store_matrix_sync(
            &C[(size_t)(m0 + wm * 16) * NTOT + n0 + wn * 32 + i * 16],
            acc[i], NTOT, wmma::mem_row_major);
    }
}

// ---------------------------------------------------------------------------
// K1: blocks 0..255 -> G1 split-K=2 fp32; 256..383 -> transpose wdown -> half.
// ---------------------------------------------------------------------------
__global__ void __launch_bounds__(256)
k1_fused(const float* __restrict__ x, const float* __restrict__ wq,
         const float* __restrict__ wdown)
{
    __shared__ __align__(16) char smem[GEMM_SMEM_BYTES];
    int bid = blockIdx.x;
    if (bid < 256) {
        int nb = bid & 7;
        int mb = (bid >> 3) & 15;
        int sp = bid >> 7;
        int koff = sp * 256;
        float* outp = sp ? g_qp1 : g_qp0;
        sgemm64<DIMV, DIMV, 16, true>(
            x + koff, wq + (size_t)koff * DIMV, outp, mb * 64, nb * 64, smem);
    } else {
        int b = bid - 256;
        int d0 = (b & 15) * 32;
        int e0 = (b >> 4) * 32;
        float (*t)[33] = (float(*)[33])smem;
        int tx = threadIdx.x & 31, ty = threadIdx.x >> 5;
#pragma unroll
        for (int i = 0; i < 4; i++)
            t[ty + i * 8][tx] = wdown[(size_t)(e0 + ty + i * 8) * DIMV + d0 + tx];
        __syncthreads();
#pragma unroll
        for (int i = 0; i < 4; i++)
            g_wdTh[(size_t)(d0 + ty + i * 8) * NUM_KEYS + e0 + tx] =
                __float2half_rn(t[tx][ty + i * 8]);
    }
}

// ---------------------------------------------------------------------------
// K2: blocks 0..63 -> G2 (D = (qp0+qp1) @ wdTh, HMMA); 64..191 -> sim (fp32).
// ---------------------------------------------------------------------------
#define SIM_SMEM_BYTES (DIM_KEY*NUM_KEYS*4 + DIM_KEY*64*4)
#define K2_SMEM (SIM_SMEM_BYTES > HGEMM_SMEM_BYTES ? SIM_SMEM_BYTES : HGEMM_SMEM_BYTES)

__global__ void __launch_bounds__(256)
k2_fused(const float* __restrict__ keys)
{
    __shared__ __align__(16) char smem[K2_SMEM];
    int bid = blockIdx.x;
    int tid = threadIdx.x;

    if (bid < 64) {
        int mb = bid >> 2, nb = bid & 3;
        hgemm_db<DIMV, NUM_KEYS, false, true>(
            g_qp0, g_qp1, g_wdTh, g_D, mb * 64, nb * 64, smem);
        return;
    }

    // sim
    int b = bid - 64;
    int t0 = (b & 15) * 64;
    int h = b >> 4;

    float (*Ks)[NUM_KEYS] = (float(*)[NUM_KEYS])smem;
    float (*Qs)[64] = (float(*)[64])(smem + DIM_KEY * NUM_KEYS * 4);

    {
        const float4* kp = reinterpret_cast<const float4*>(
            keys + (size_t)((h * NUM_KEYS + tid) * 2) * DIM_KEY);
#pragma unroll
        for (int i = 0; i < 8; i++) {
            float4 f = kp[i];
            Ks[4 * i + 0][tid] = f.x;
            Ks[4 * i + 1][tid] = f.y;
            Ks[4 * i + 2][tid] = f.z;
            Ks[4 * i + 3][tid] = f.w;
        }
    }
    {
        int tl = tid & 63;
        int d0 = (tid >> 6) * 8;
        size_t off = (size_t)(t0 + tl) * DIMV + h * DIM_KEY + d0;
        float4 f0 = *reinterpret_cast<const float4*>(g_qp0 + off);
        float4 f1 = *reinterpret_cast<const float4*>(g_qp0 + off + 4);
        float4 e0 = *reinterpret_cast<const float4*>(g_qp1 + off);
        float4 e1 = *reinterpret_cast<const float4*>(g_qp1 + off + 4);
        f0.x += e0.x; f0.y += e0.y; f0.z += e0.z; f0.w += e0.w;
        f1.x += e1.x; f1.y += e1.y; f1.z += e1.z; f1.w += e1.w;
        Qs[d0 + 0][tl] = f0.x; Qs[d0 + 1][tl] = f0.y;
        Qs[d0 + 2][tl] = f0.z; Qs[d0 + 3][tl] = f0.w;
        Qs[d0 + 4][tl] = f1.x; Qs[d0 + 5][tl] = f1.y;
        Qs[d0 + 6][tl] = f1.z; Qs[d0 + 7][tl] = f1.w;
    }
    __syncthreads();

    int kg = tid & 15;
    int tg = tid >> 4;
    float acc[4][16];
#pragma unroll
    for (int i = 0; i < 4; i++)
#pragma unroll
        for (int j = 0; j < 16; j++) acc[i][j] = 0.0f;

#pragma unroll
    for (int d = 0; d < DIM_KEY; d++) {
        float4 qv = *reinterpret_cast<const float4*>(&Qs[d][tg * 4]);
        float q4[4] = {qv.x, qv.y, qv.z, qv.w};
        float kv[16];
#pragma unroll
        for (int jj = 0; jj < 4; jj++) {
            float4 kk = *reinterpret_cast<const float4*>(&Ks[d][kg * 16 + jj * 4]);
            kv[jj * 4 + 0] = kk.x; kv[jj * 4 + 1] = kk.y;
            kv[jj * 4 + 2] = kk.z; kv[jj * 4 + 3] = kk.w;
        }
#pragma unroll
        for (int i = 0; i < 4; i++)
#pragma unroll
            for (int j = 0; j < 16; j++) acc[i][j] += q4[i] * kv[j];
    }

#pragma unroll
    for (int i = 0; i < 4; i++) {
        int t = t0 + tg * 4 + i;
        float* op = g_sim + ((size_t)h * TOKENS + t) * NUM_KEYS + kg * 16;
#pragma unroll
        for (int jj = 0; jj < 4; jj++) {
            float4 f;
            f.x = acc[i][jj * 4 + 0]; f.y = acc[i][jj * 4 + 1];
            f.z = acc[i][jj * 4 + 2]; f.w = acc[i][jj * 4 + 3];
            *reinterpret_cast<float4*>(op + jj * 4) = f;
        }
    }
}

// ---------------------------------------------------------------------------
// K3: selection with structural fast path.
// ---------------------------------------------------------------------------
__device__ __forceinline__ float gelu_tanh(float x) {
    float x3 = x * x * x;
    float t = tanhf(0.7978845608028654f * (x + 0.044715f * x3));
    return 0.5f * x * (1.0f + t);
}

__device__ __forceinline__ void warp_top16(float* val, int lane,
                                           float* out_v, int* out_i)
{
#pragma unroll
    for (int r = 0; r < TOPK; r++) {
        float bv = val[0]; int bs = 0;
#pragma unroll
        for (int s = 1; s < 8; s++)
            if (val[s] > bv) { bv = val[s]; bs = s; }
        int bp = lane + (bs << 5);
#pragma unroll
        for (int off = 16; off > 0; off >>= 1) {
            float ov = __shfl_xor_sync(FULLMASK, bv, off);
            int   op = __shfl_xor_sync(FULLMASK, bp, off);
            if (ov > bv || (ov == bv && op < bp)) { bv = ov; bp = op; }
        }
        out_v[r] = bv;
        out_i[r] = bp;
        if ((bp & 31) == lane) {
            int ws = bp >> 5;
#pragma unroll
            for (int s = 0; s < 8; s++)
                if (s == ws) val[s] = -INFINITY;
        }
    }
}

__global__ void __launch_bounds__(256) select_kernel()
{
    int t = blockIdx.x;
    int tid = threadIdx.x;
    int w = tid >> 5;
    int lane = tid & 31;

    __shared__ float sS[NUM_KEYS];
    __shared__ float v0s[HEADS][TOPK];
    __shared__ float i0s[HEADS][TOPK];

    sS[tid] = 0.0f;
    __syncthreads();

    float val[8];
    {
        const float* simrow = g_sim + ((size_t)w * TOKENS + t) * NUM_KEYS;
#pragma unroll
        for (int s = 0; s < 8; s++)
            val[s] = simrow[lane + (s << 5)];
    }

    float v0[TOPK]; int i0[TOPK];
    warp_top16(val, lane, v0, i0);

    int imax = -1, i2nd = -1, jst = 0;
#pragma unroll
    for (int j = 0; j < TOPK; j++) {
        int v = i0[j];
        if (v > imax) { i2nd = imax; imax = v; jst = j; }
        else if (v > i2nd) i2nd = v;
    }
    float spread = v0[0] - v0[TOPK - 1];
    bool fast = (float)(imax - i2nd) > spread;

    if (fast) {
        float myv = -INFINITY;
#pragma unroll
        for (int r = 0; r < TOPK; r++)
            if (lane == r) myv = v0[r];
        float mye = expf(myv - v0[0]);
        float esum = mye;
#pragma unroll
        for (int off = 16; off > 0; off >>= 1)
            esum += __shfl_xor_sync(FULLMASK, esum, off);
        if (lane < TOPK) {
            int pk = lane * TOPK + jst;
            float dv = g_D[(size_t)t * NUM_KEYS + pk];
            float g = gelu_tanh(dv) * (mye / esum);
            atomicAdd(&sS[pk], g);
        }
    } else {
        if (lane == 0) {
#pragma unroll
            for (int r = 0; r < TOPK; r++) {
                v0s[w][r] = v0[r];
                i0s[w][r] = (float)i0[r];
            }
        }
        __syncwarp();
        float val2[8];
#pragma unroll
        for (int s = 0; s < 8; s++) {
            int p = lane + (s << 5);
            val2[s] = v0s[w][p >> 4] + i0s[w][p & 15];
        }
        float scf[TOPK]; int pk[TOPK];
        warp_top16(val2, lane, scf, pk);

        float myscf = -INFINITY; int mypk = 0;
#pragma unroll
        for (int r = 0; r < TOPK; r++)
            if (lane == r) { myscf = scf[r]; mypk = pk[r]; }
        float m = scf[0];
#pragma unroll
        for (int r = 1; r < TOPK; r++) m = fmaxf(m, scf[r]);
        float mye = expf(myscf - m);
        float esum = mye;
#pragma unroll
        for (int off = 16; off > 0; off >>= 1)
            esum += __shfl_xor_sync(FULLMASK, esum, off);
        if (lane < TOPK) {
            float dv = g_D[(size_t)t * NUM_KEYS + mypk];
            float g = gelu_tanh(dv) * (mye / esum);
            atomicAdd(&sS[mypk], g);
        }
    }
    __syncthreads();

    g_Sh[(size_t)t * NUM_KEYS + tid] = __float2half_rn(sS[tid]);
}

// ---------------------------------------------------------------------------
// K4: out = Sh @ wup[:256]  (HMMA, fp32 out)
// ---------------------------------------------------------------------------
__global__ void __launch_bounds__(256)
k4_gemm(const float* __restrict__ wup, float* __restrict__ out)
{
    __shared__ __align__(16) char smem[HGEMM_SMEM_BYTES];
    int bid = blockIdx.x;
    int mb = bid >> 3, nb = bid & 7;
    hgemm_db<NUM_KEYS, DIMV, true, false>(
        g_Sh, nullptr, wup, out, mb * 64, nb * 64, smem);
}

// ---------------------------------------------------------------------------
extern "C" void kernel_launch(void* const* d_in, const int* in_sizes, int n_in,
                              void* d_out, int out_size)
{
    const float* x     = (const float*)d_in[0];
    const float* w_q   = (const float*)d_in[1];
    const float* keys  = (const float*)d_in[2];
    const float* wdown = (const float*)d_in[3];
    const float* wup   = (const float*)d_in[4];
    float* out = (float*)d_out;

    k1_fused<<<384, 256>>>(x, w_q, wdown);
    k2_fused<<<192, 256>>>(keys);
    select_kernel<<<TOKENS, 256>>>();
    k4_gemm<<<128, 256>>>(wup, out);
}

// round 10
// speedup vs baseline: 1.4729x; 1.0804x over previous
#include <cuda_runtime.h>
#include <cuda_fp16.h>
#include <mma.h>
#include <math.h>

using namespace nvcuda;

#define DIMV       512
#define HEADS      8
#define DIM_KEY    32
#define NUM_KEYS   256
#define TOPK       16
#define TOKENS     1024
#define FULLMASK   0xffffffffu

// scratch (device globals; no allocs)
__device__ __align__(16) float  g_q  [TOKENS * DIMV];    // exact q (split-GEMM)
__device__ __align__(16) __half g_qh [TOKENS * DIMV];    // fp16 q for G2
__device__ __align__(16) float  g_sim[HEADS * TOKENS * NUM_KEYS];
__device__ __align__(16) __half g_wdTh[DIMV * NUM_KEYS];
__device__ __align__(16) float  g_D  [TOKENS * NUM_KEYS];
__device__ __align__(16) __half g_Sh [TOKENS * NUM_KEYS];

// ---------------------------------------------------------------------------
// helpers
// ---------------------------------------------------------------------------
__device__ __forceinline__ uint4 pack8h(float4 f0, float4 f1) {
    __half2 h0 = __floats2half2_rn(f0.x, f0.y);
    __half2 h1 = __floats2half2_rn(f0.z, f0.w);
    __half2 h2 = __floats2half2_rn(f1.x, f1.y);
    __half2 h3 = __floats2half2_rn(f1.z, f1.w);
    uint4 u;
    u.x = *reinterpret_cast<unsigned*>(&h0);
    u.y = *reinterpret_cast<unsigned*>(&h1);
    u.z = *reinterpret_cast<unsigned*>(&h2);
    u.w = *reinterpret_cast<unsigned*>(&h3);
    return u;
}

// load 8 fp32, split into fp16 hi + fp16 residual
__device__ __forceinline__ void split8(const float* p, uint4& hi, uint4& lo) {
    float4 f0 = *reinterpret_cast<const float4*>(p);
    float4 f1 = *reinterpret_cast<const float4*>(p + 4);
    float v[8] = {f0.x, f0.y, f0.z, f0.w, f1.x, f1.y, f1.z, f1.w};
    __align__(16) __half h[8];
    __align__(16) __half l[8];
#pragma unroll
    for (int i = 0; i < 8; i++) {
        h[i] = __float2half_rn(v[i]);
        l[i] = __float2half_rn(v[i] - __half2float(h[i]));
    }
    hi = *reinterpret_cast<uint4*>(h);
    lo = *reinterpret_cast<uint4*>(l);
}

// ---------------------------------------------------------------------------
// G1: split fp16 GEMM, 64x64 tile, 256 threads, BK=32, double-buffered.
// q = (x @ wq) * scale, computed as xh*wh + xh*wl + xl*wh (fp32 accum).
// Outputs both fp32 g_q and fp16 g_qh.
// smem: Ah[2][64][40] Al[2][64][40] (10240B each), Bh[2][32][72] Bl (9216B each)
// ---------------------------------------------------------------------------
#define K1_SMEM_BYTES (10240 + 10240 + 9216 + 9216)

__device__ __forceinline__ void g1_split_gemm(
    const float* __restrict__ x, const float* __restrict__ wq,
    int m0, int n0, char* smem_raw)
{
    typedef __half A_t[64][40];
    typedef __half B_t[32][72];
    A_t* Ah = (A_t*)smem_raw;
    A_t* Al = (A_t*)(smem_raw + 10240);
    B_t* Bh = (B_t*)(smem_raw + 20480);
    B_t* Bl = (B_t*)(smem_raw + 29696);

    const int tid = threadIdx.x;
    const int w = tid >> 5;
    const int wm = w >> 1;           // 0..3
    const int wn = w & 1;            // 0..1

    const int arow = tid >> 2;       // 0..63
    const int akq  = (tid & 3) * 8;  // 0,8,16,24
    const int brow = tid >> 3;       // 0..31
    const int bnq  = (tid & 7) * 8;  // 0..56

    wmma::fragment<wmma::accumulator, 16, 16, 16, float> acc[2];
    wmma::fill_fragment(acc[0], 0.0f);
    wmma::fill_fragment(acc[1], 0.0f);

    uint4 ah, al, bh, bl;
    split8(&x [(size_t)(m0 + arow) * DIMV + akq], ah, al);
    split8(&wq[(size_t)brow * DIMV + n0 + bnq], bh, bl);

    int buf = 0;
    const int NT = DIMV / 32;   // 16
#pragma unroll 1
    for (int kt = 0; kt < NT; kt++) {
        *reinterpret_cast<uint4*>(&Ah[buf][arow][akq]) = ah;
        *reinterpret_cast<uint4*>(&Al[buf][arow][akq]) = al;
        *reinterpret_cast<uint4*>(&Bh[buf][brow][bnq]) = bh;
        *reinterpret_cast<uint4*>(&Bl[buf][brow][bnq]) = bl;
        __syncthreads();

        if (kt + 1 < NT) {
            int k0 = (kt + 1) * 32;
            split8(&x [(size_t)(m0 + arow) * DIMV + k0 + akq], ah, al);
            split8(&wq[(size_t)(k0 + brow) * DIMV + n0 + bnq], bh, bl);
        }

        wmma::fragment<wmma::matrix_a, 16, 16, 16, __half, wmma::row_major> afh, afl;
        wmma::fragment<wmma::matrix_b, 16, 16, 16, __half, wmma::row_major> bfh, bfl;
#pragma unroll
        for (int ks = 0; ks < 2; ks++) {
            wmma::load_matrix_sync(afh, &Ah[buf][wm * 16][ks * 16], 40);
            wmma::load_matrix_sync(afl, &Al[buf][wm * 16][ks * 16], 40);
#pragma unroll
            for (int i = 0; i < 2; i++) {
                wmma::load_matrix_sync(bfh, &Bh[buf][ks * 16][wn * 32 + i * 16], 72);
                wmma::load_matrix_sync(bfl, &Bl[buf][ks * 16][wn * 32 + i * 16], 72);
                wmma::mma_sync(acc[i], afh, bfh, acc[i]);
                wmma::mma_sync(acc[i], afh, bfl, acc[i]);
                wmma::mma_sync(acc[i], afl, bfh, acc[i]);
            }
        }
        buf ^= 1;
    }

    // epilogue via smem: write fp32 q and fp16 qh
    __syncthreads();
    float (*Cs)[68] = (float(*)[68])smem_raw;
#pragma unroll
    for (int i = 0; i < 2; i++)
        wmma::store_matrix_sync(&Cs[wm * 16][wn * 32 + i * 16], acc[i], 68,
                                wmma::mem_row_major);
    __syncthreads();

    const float scale = 0.99999500003749981f;
    int trow = tid >> 2;
    int tc0  = (tid & 3) * 16;
    float4 fo[4];
#pragma unroll
    for (int j = 0; j < 4; j++) {
        float4 f = *reinterpret_cast<const float4*>(&Cs[trow][tc0 + j * 4]);
        f.x *= scale; f.y *= scale; f.z *= scale; f.w *= scale;
        fo[j] = f;
        *reinterpret_cast<float4*>(
            &g_q[(size_t)(m0 + trow) * DIMV + n0 + tc0 + j * 4]) = f;
    }
    uint4 hq0 = pack8h(fo[0], fo[1]);
    uint4 hq1 = pack8h(fo[2], fo[3]);
    __half* qh = &g_qh[(size_t)(m0 + trow) * DIMV + n0 + tc0];
    *reinterpret_cast<uint4*>(qh)     = hq0;
    *reinterpret_cast<uint4*>(qh + 8) = hq1;
}

// ---------------------------------------------------------------------------
// fp16 WMMA GEMM, double-buffered: 64x64 C tile, 256 threads, BK=32.
// A: [M][K] half. B: [K][NTOT] half or fp32 (converted inline).
// smem: As[2][64][40] (10240B) + Bs[2][32][72] (9216B)
// ---------------------------------------------------------------------------
#define HGEMM_SMEM_BYTES (2*64*40*2 + 2*32*72*2)

template<int K, int NTOT, bool BHALF>
__device__ __forceinline__ void hgemm_db(
    const __half* __restrict__ Av, const void* __restrict__ Bv,
    float* __restrict__ C, int m0, int n0, char* smem_raw)
{
    typedef __half AsT[64][40];
    typedef __half BsT[32][72];
    AsT* As = (AsT*)smem_raw;
    BsT* Bs = (BsT*)(smem_raw + 2 * 64 * 40 * 2);

    const int tid = threadIdx.x;
    const int w = tid >> 5;
    const int wm = w >> 1;
    const int wn = w & 1;

    const int arow = tid >> 2;
    const int akq  = (tid & 3) * 8;
    const int brow = tid >> 3;
    const int bnq  = (tid & 7) * 8;

    wmma::fragment<wmma::accumulator, 16, 16, 16, float> acc[2];
    wmma::fill_fragment(acc[0], 0.0f);
    wmma::fill_fragment(acc[1], 0.0f);

    uint4 areg, breg;
    areg = *reinterpret_cast<const uint4*>(Av + (size_t)(m0 + arow) * K + akq);
    if (BHALF) {
        breg = *reinterpret_cast<const uint4*>(
            (const __half*)Bv + (size_t)brow * NTOT + n0 + bnq);
    } else {
        const float* b = (const float*)Bv + (size_t)brow * NTOT + n0 + bnq;
        breg = pack8h(*reinterpret_cast<const float4*>(b),
                      *reinterpret_cast<const float4*>(b + 4));
    }

    int buf = 0;
    const int NT = K / 32;
#pragma unroll 1
    for (int kt = 0; kt < NT; kt++) {
        *reinterpret_cast<uint4*>(&As[buf][arow][akq]) = areg;
        *reinterpret_cast<uint4*>(&Bs[buf][brow][bnq]) = breg;
        __syncthreads();

        if (kt + 1 < NT) {
            int k0 = (kt + 1) * 32;
            areg = *reinterpret_cast<const uint4*>(
                Av + (size_t)(m0 + arow) * K + k0 + akq);
            if (BHALF) {
                breg = *reinterpret_cast<const uint4*>(
                    (const __half*)Bv + (size_t)(k0 + brow) * NTOT + n0 + bnq);
            } else {
                const float* b = (const float*)Bv + (size_t)(k0 + brow) * NTOT + n0 + bnq;
                breg = pack8h(*reinterpret_cast<const float4*>(b),
                              *reinterpret_cast<const float4*>(b + 4));
            }
        }

        wmma::fragment<wmma::matrix_a, 16, 16, 16, __half, wmma::row_major> af;
        wmma::fragment<wmma::matrix_b, 16, 16, 16, __half, wmma::row_major> bf;
#pragma unroll
        for (int ks = 0; ks < 2; ks++) {
            wmma::load_matrix_sync(af, &As[buf][wm * 16][ks * 16], 40);
#pragma unroll
            for (int i = 0; i < 2; i++) {
                wmma::load_matrix_sync(bf, &Bs[buf][ks * 16][wn * 32 + i * 16], 72);
                wmma::mma_sync(acc[i], af, bf, acc[i]);
            }
        }
        buf ^= 1;
    }

#pragma unroll
    for (int i = 0; i < 2; i++) {
        wmma::store_matrix_sync(
            &C[(size_t)(m0 + wm * 16) * NTOT + n0 + wn * 32 + i * 16],
            acc[i], NTOT, wmma::mem_row_major);
    }
}

// ---------------------------------------------------------------------------
// K1: blocks 0..127 -> G1 split GEMM; 128..255 -> transpose wdown -> half.
// ---------------------------------------------------------------------------
__global__ void __launch_bounds__(256)
k1_fused(const float* __restrict__ x, const float* __restrict__ wq,
         const float* __restrict__ wdown)
{
    __shared__ __align__(16) char smem[K1_SMEM_BYTES];
    int bid = blockIdx.x;
    if (bid < 128) {
        int mb = bid >> 3, nb = bid & 7;
        g1_split_gemm(x, wq, mb * 64, nb * 64, smem);
    } else {
        int b = bid - 128;
        int d0 = (b & 15) * 32;
        int e0 = (b >> 4) * 32;
        float (*t)[33] = (float(*)[33])smem;
        int tx = threadIdx.x & 31, ty = threadIdx.x >> 5;
#pragma unroll
        for (int i = 0; i < 4; i++)
            t[ty + i * 8][tx] = wdown[(size_t)(e0 + ty + i * 8) * DIMV + d0 + tx];
        __syncthreads();
#pragma unroll
        for (int i = 0; i < 4; i++)
            g_wdTh[(size_t)(d0 + ty + i * 8) * NUM_KEYS + e0 + tx] =
                __float2half_rn(t[tx][ty + i * 8]);
    }
}

// ---------------------------------------------------------------------------
// K2: blocks 0..63 -> G2 (D = qh @ wdTh, HMMA); 64..191 -> sim (fp32).
// ---------------------------------------------------------------------------
#define SIM_SMEM_BYTES (DIM_KEY*NUM_KEYS*4 + DIM_KEY*64*4)
#define K2_SMEM (SIM_SMEM_BYTES > HGEMM_SMEM_BYTES ? SIM_SMEM_BYTES : HGEMM_SMEM_BYTES)

__global__ void __launch_bounds__(256)
k2_fused(const float* __restrict__ keys)
{
    __shared__ __align__(16) char smem[K2_SMEM];
    int bid = blockIdx.x;
    int tid = threadIdx.x;

    if (bid < 64) {
        int mb = bid >> 2, nb = bid & 3;
        hgemm_db<DIMV, NUM_KEYS, true>(
            g_qh, g_wdTh, g_D, mb * 64, nb * 64, smem);
        return;
    }

    // sim
    int b = bid - 64;
    int t0 = (b & 15) * 64;
    int h = b >> 4;

    float (*Ks)[NUM_KEYS] = (float(*)[NUM_KEYS])smem;
    float (*Qs)[64] = (float(*)[64])(smem + DIM_KEY * NUM_KEYS * 4);

    {
        const float4* kp = reinterpret_cast<const float4*>(
            keys + (size_t)((h * NUM_KEYS + tid) * 2) * DIM_KEY);
#pragma unroll
        for (int i = 0; i < 8; i++) {
            float4 f = kp[i];
            Ks[4 * i + 0][tid] = f.x;
            Ks[4 * i + 1][tid] = f.y;
            Ks[4 * i + 2][tid] = f.z;
            Ks[4 * i + 3][tid] = f.w;
        }
    }
    {
        int tl = tid & 63;
        int d0 = (tid >> 6) * 8;
        size_t off = (size_t)(t0 + tl) * DIMV + h * DIM_KEY + d0;
        float4 f0 = *reinterpret_cast<const float4*>(g_q + off);
        float4 f1 = *reinterpret_cast<const float4*>(g_q + off + 4);
        Qs[d0 + 0][tl] = f0.x; Qs[d0 + 1][tl] = f0.y;
        Qs[d0 + 2][tl] = f0.z; Qs[d0 + 3][tl] = f0.w;
        Qs[d0 + 4][tl] = f1.x; Qs[d0 + 5][tl] = f1.y;
        Qs[d0 + 6][tl] = f1.z; Qs[d0 + 7][tl] = f1.w;
    }
    __syncthreads();

    int kg = tid & 15;
    int tg = tid >> 4;
    float acc[4][16];
#pragma unroll
    for (int i = 0; i < 4; i++)
#pragma unroll
        for (int j = 0; j < 16; j++) acc[i][j] = 0.0f;

#pragma unroll
    for (int d = 0; d < DIM_KEY; d++) {
        float4 qv = *reinterpret_cast<const float4*>(&Qs[d][tg * 4]);
        float q4[4] = {qv.x, qv.y, qv.z, qv.w};
        float kv[16];
#pragma unroll
        for (int jj = 0; jj < 4; jj++) {
            float4 kk = *reinterpret_cast<const float4*>(&Ks[d][kg * 16 + jj * 4]);
            kv[jj * 4 + 0] = kk.x; kv[jj * 4 + 1] = kk.y;
            kv[jj * 4 + 2] = kk.z; kv[jj * 4 + 3] = kk.w;
        }
#pragma unroll
        for (int i = 0; i < 4; i++)
#pragma unroll
            for (int j = 0; j < 16; j++) acc[i][j] += q4[i] * kv[j];
    }

#pragma unroll
    for (int i = 0; i < 4; i++) {
        int t = t0 + tg * 4 + i;
        float* op = g_sim + ((size_t)h * TOKENS + t) * NUM_KEYS + kg * 16;
#pragma unroll
        for (int jj = 0; jj < 4; jj++) {
            float4 f;
            f.x = acc[i][jj * 4 + 0]; f.y = acc[i][jj * 4 + 1];
            f.z = acc[i][jj * 4 + 2]; f.w = acc[i][jj * 4 + 3];
            *reinterpret_cast<float4*>(op + jj * 4) = f;
        }
    }
}

// ---------------------------------------------------------------------------
// K3: selection with structural fast path.
// ---------------------------------------------------------------------------
__device__ __forceinline__ float gelu_tanh(float x) {
    float x3 = x * x * x;
    float t = tanhf(0.7978845608028654f * (x + 0.044715f * x3));
    return 0.5f * x * (1.0f + t);
}

__device__ __forceinline__ void warp_top16(float* val, int lane,
                                           float* out_v, int* out_i)
{
#pragma unroll
    for (int r = 0; r < TOPK; r++) {
        float bv = val[0]; int bs = 0;
#pragma unroll
        for (int s = 1; s < 8; s++)
            if (val[s] > bv) { bv = val[s]; bs = s; }
        int bp = lane + (bs << 5);
#pragma unroll
        for (int off = 16; off > 0; off >>= 1) {
            float ov = __shfl_xor_sync(FULLMASK, bv, off);
            int   op = __shfl_xor_sync(FULLMASK, bp, off);
            if (ov > bv || (ov == bv && op < bp)) { bv = ov; bp = op; }
        }
        out_v[r] = bv;
        out_i[r] = bp;
        if ((bp & 31) == lane) {
            int ws = bp >> 5;
#pragma unroll
            for (int s = 0; s < 8; s++)
                if (s == ws) val[s] = -INFINITY;
        }
    }
}

__global__ void __launch_bounds__(256) select_kernel()
{
    int t = blockIdx.x;
    int tid = threadIdx.x;
    int w = tid >> 5;
    int lane = tid & 31;

    __shared__ float sS[NUM_KEYS];
    __shared__ float v0s[HEADS][TOPK];
    __shared__ float i0s[HEADS][TOPK];

    sS[tid] = 0.0f;
    __syncthreads();

    float val[8];
    {
        const float* simrow = g_sim + ((size_t)w * TOKENS + t) * NUM_KEYS;
#pragma unroll
        for (int s = 0; s < 8; s++)
            val[s] = simrow[lane + (s << 5)];
    }

    float v0[TOPK]; int i0[TOPK];
    warp_top16(val, lane, v0, i0);

    int imax = -1, i2nd = -1, jst = 0;
#pragma unroll
    for (int j = 0; j < TOPK; j++) {
        int v = i0[j];
        if (v > imax) { i2nd = imax; imax = v; jst = j; }
        else if (v > i2nd) i2nd = v;
    }
    float spread = v0[0] - v0[TOPK - 1];
    bool fast = (float)(imax - i2nd) > spread;

    if (fast) {
        float myv = -INFINITY;
#pragma unroll
        for (int r = 0; r < TOPK; r++)
            if (lane == r) myv = v0[r];
        float mye = expf(myv - v0[0]);
        float esum = mye;
#pragma unroll
        for (int off = 16; off > 0; off >>= 1)
            esum += __shfl_xor_sync(FULLMASK, esum, off);
        if (lane < TOPK) {
            int pk = lane * TOPK + jst;
            float dv = g_D[(size_t)t * NUM_KEYS + pk];
            float g = gelu_tanh(dv) * (mye / esum);
            atomicAdd(&sS[pk], g);
        }
    } else {
        if (lane == 0) {
#pragma unroll
            for (int r = 0; r < TOPK; r++) {
                v0s[w][r] = v0[r];
                i0s[w][r] = (float)i0[r];
            }
        }
        __syncwarp();
        float val2[8];
#pragma unroll
        for (int s = 0; s < 8; s++) {
            int p = lane + (s << 5);
            val2[s] = v0s[w][p >> 4] + i0s[w][p & 15];
        }
        float scf[TOPK]; int pk[TOPK];
        warp_top16(val2, lane, scf, pk);

        float myscf = -INFINITY; int mypk = 0;
#pragma unroll
        for (int r = 0; r < TOPK; r++)
            if (lane == r) { myscf = scf[r]; mypk = pk[r]; }
        float m = scf[0];
#pragma unroll
        for (int r = 1; r < TOPK; r++) m = fmaxf(m, scf[r]);
        float mye = expf(myscf - m);
        float esum = mye;
#pragma unroll
        for (int off = 16; off > 0; off >>= 1)
            esum += __shfl_xor_sync(FULLMASK, esum, off);
        if (lane < TOPK) {
            float dv = g_D[(size_t)t * NUM_KEYS + mypk];
            float g = gelu_tanh(dv) * (mye / esum);
            atomicAdd(&sS[mypk], g);
        }
    }
    __syncthreads();

    g_Sh[(size_t)t * NUM_KEYS + tid] = __float2half_rn(sS[tid]);
}

// ---------------------------------------------------------------------------
// K4: out = Sh @ wup[:256]  (HMMA, fp32 out)
// ---------------------------------------------------------------------------
__global__ void __launch_bounds__(256)
k4_gemm(const float* __restrict__ wup, float* __restrict__ out)
{
    __shared__ __align__(16) char smem[HGEMM_SMEM_BYTES];
    int bid = blockIdx.x;
    int mb = bid >> 3, nb = bid & 7;
    hgemm_db<NUM_KEYS, DIMV, false>(
        g_Sh, wup, out, mb * 64, nb * 64, smem);
}

// ---------------------------------------------------------------------------
extern "C" void kernel_launch(void* const* d_in, const int* in_sizes, int n_in,
                              void* d_out, int out_size)
{
    const float* x     = (const float*)d_in[0];
    const float* w_q   = (const float*)d_in[1];
    const float* keys  = (const float*)d_in[2];
    const float* wdown = (const float*)d_in[3];
    const float* wup   = (const float*)d_in[4];
    float* out = (float*)d_out;

    k1_fused<<<256, 256>>>(x, w_q, wdown);
    k2_fused<<<192, 256>>>(keys);
    select_kernel<<<TOKENS, 256>>>();
    k4_gemm<<<128, 256>>>(wup, out);
}